// round 1
// baseline (speedup 1.0000x reference)
#include <cuda_runtime.h>

#define BB 2
#define LL 1536
#define DD 1024
#define HH 16
#define PP 1024
#define HDIM 64
#define NTH 256
#define PER (LL / NTH)   // 6

// ---------------- device scratch (no allocations allowed) ----------------
__device__ float g_Q[BB * HH * LL * HDIM];      // 12.6 MB, head-major [b,h,l,d]
__device__ float g_K[BB * HH * LL * HDIM];
__device__ float g_V[BB * HH * LL * HDIM];
__device__ float g_attn[BB * LL * PP];          // 12.6 MB, [b,l,h*64+d]
__device__ float g_S[BB * HH * LL * LL];        // 302 MB, scores -> p in-place

// ---------------- block reductions (256 threads) ----------------
__device__ __forceinline__ float block_sum(float v, float* red) {
    __syncthreads();
#pragma unroll
    for (int o = 16; o > 0; o >>= 1) v += __shfl_xor_sync(0xffffffffu, v, o);
    if ((threadIdx.x & 31) == 0) red[threadIdx.x >> 5] = v;
    __syncthreads();
    float s = 0.f;
#pragma unroll
    for (int j = 0; j < 8; j++) s += red[j];
    return s;
}

__device__ __forceinline__ float block_max(float v, float* red) {
    __syncthreads();
#pragma unroll
    for (int o = 16; o > 0; o >>= 1) v = fmaxf(v, __shfl_xor_sync(0xffffffffu, v, o));
    if ((threadIdx.x & 31) == 0) red[threadIdx.x >> 5] = v;
    __syncthreads();
    float s = red[0];
#pragma unroll
    for (int j = 1; j < 8; j++) s = fmaxf(s, red[j]);
    return s;
}

// ---------------- projection GEMM: C = A @ W + bias ----------------
// A [3072,1024] row-major, W [1024,1024] row-major.
// mode 0/1/2: write Q/K/V in head-major [b,h,l,d]. mode 3: flat to Cout (A = g_attn).
__global__ __launch_bounds__(256) void proj_gemm(const float* __restrict__ Ain,
                                                 const float* __restrict__ W,
                                                 const float* __restrict__ bias,
                                                 float* __restrict__ Cout, int mode) {
    const float* A = (mode == 3) ? g_attn : Ain;
    float* C;
    if (mode == 0) C = g_Q;
    else if (mode == 1) C = g_K;
    else if (mode == 2) C = g_V;
    else C = Cout;

    const int m0 = blockIdx.y * 64;
    const int n0 = blockIdx.x * 64;

    __shared__ float As[64][20];   // [m][k], row stride 80B (16B aligned)
    __shared__ float Bs[16][68];   // [k][n], row stride 272B (16B aligned)

    const int t = threadIdx.x;
    const int tx = t & 15, ty = t >> 4;
    const int am = t >> 2, ak = (t & 3) * 4;
    const int bk = t >> 4, bn = (t & 15) * 4;

    float acc[4][4] = {};
    const float* Aptr = A + (size_t)(m0 + am) * DD + ak;
    const float* Wptr = W + (size_t)bk * PP + n0 + bn;

    for (int k0 = 0; k0 < DD; k0 += 16) {
        float4 a4 = *(const float4*)(Aptr + k0);
        *(float4*)&As[am][ak] = a4;
        float4 b4 = *(const float4*)(Wptr + (size_t)k0 * PP);
        *(float4*)&Bs[bk][bn] = b4;
        __syncthreads();
#pragma unroll
        for (int kk = 0; kk < 16; kk++) {
            float a0 = As[ty * 4 + 0][kk], a1 = As[ty * 4 + 1][kk];
            float a2 = As[ty * 4 + 2][kk], a3 = As[ty * 4 + 3][kk];
            float4 b = *(float4*)&Bs[kk][tx * 4];
            acc[0][0] += a0 * b.x; acc[0][1] += a0 * b.y; acc[0][2] += a0 * b.z; acc[0][3] += a0 * b.w;
            acc[1][0] += a1 * b.x; acc[1][1] += a1 * b.y; acc[1][2] += a1 * b.z; acc[1][3] += a1 * b.w;
            acc[2][0] += a2 * b.x; acc[2][1] += a2 * b.y; acc[2][2] += a2 * b.z; acc[2][3] += a2 * b.w;
            acc[3][0] += a3 * b.x; acc[3][1] += a3 * b.y; acc[3][2] += a3 * b.z; acc[3][3] += a3 * b.w;
        }
        __syncthreads();
    }

    float4 bb = *(const float4*)(bias + n0 + tx * 4);
    if (mode <= 2) {
        // head-major: tile is entirely within one b (L%64==0) and one h (64-wide tiles)
        const int b = m0 / LL;
        const int h = n0 >> 6;
        float* Cb = C + (((size_t)(b * HH + h)) * LL + (m0 - b * LL)) * HDIM + tx * 4;
#pragma unroll
        for (int i = 0; i < 4; i++) {
            float4 o = make_float4(acc[i][0] + bb.x, acc[i][1] + bb.y,
                                   acc[i][2] + bb.z, acc[i][3] + bb.w);
            *(float4*)(Cb + (size_t)(ty * 4 + i) * HDIM) = o;
        }
    } else {
        float* Cb = C + (size_t)m0 * DD + n0 + tx * 4;
#pragma unroll
        for (int i = 0; i < 4; i++) {
            float4 o = make_float4(acc[i][0] + bb.x, acc[i][1] + bb.y,
                                   acc[i][2] + bb.z, acc[i][3] + bb.w);
            *(float4*)(Cb + (size_t)(ty * 4 + i) * DD) = o;
        }
    }
}

// ---------------- scores: S[z][q][k] = 0.125 * sum_d Q[z][q][d]*K[z][k][d] ----------------
__global__ __launch_bounds__(256) void scores_kernel() {
    const int z = blockIdx.z;
    const float* Qb = g_Q + (size_t)z * LL * HDIM;
    const float* Kb = g_K + (size_t)z * LL * HDIM;
    float* Sb = g_S + (size_t)z * LL * LL;
    const int q0 = blockIdx.y * 64;
    const int k0 = blockIdx.x * 64;

    __shared__ float Qs[64][68];   // [q][d]
    __shared__ float Ks[64][68];   // [d][n]  (transposed on load)

    const int t = threadIdx.x;
#pragma unroll
    for (int r = 0; r < 4; r++) {
        int idx = t + r * 256;
        int row = idx >> 4;
        int c = (idx & 15) * 4;
        float4 q4 = *(const float4*)(Qb + (size_t)(q0 + row) * HDIM + c);
        *(float4*)&Qs[row][c] = q4;
        float4 k4 = *(const float4*)(Kb + (size_t)(k0 + row) * HDIM + c);
        Ks[c + 0][row] = k4.x; Ks[c + 1][row] = k4.y;
        Ks[c + 2][row] = k4.z; Ks[c + 3][row] = k4.w;
    }
    __syncthreads();

    const int tx = t & 15, ty = t >> 4;
    float acc[4][4] = {};
#pragma unroll
    for (int kk = 0; kk < 64; kk++) {
        float a0 = Qs[ty * 4 + 0][kk], a1 = Qs[ty * 4 + 1][kk];
        float a2 = Qs[ty * 4 + 2][kk], a3 = Qs[ty * 4 + 3][kk];
        float4 b = *(float4*)&Ks[kk][tx * 4];
        acc[0][0] += a0 * b.x; acc[0][1] += a0 * b.y; acc[0][2] += a0 * b.z; acc[0][3] += a0 * b.w;
        acc[1][0] += a1 * b.x; acc[1][1] += a1 * b.y; acc[1][2] += a1 * b.z; acc[1][3] += a1 * b.w;
        acc[2][0] += a2 * b.x; acc[2][1] += a2 * b.y; acc[2][2] += a2 * b.z; acc[2][3] += a2 * b.w;
        acc[3][0] += a3 * b.x; acc[3][1] += a3 * b.y; acc[3][2] += a3 * b.z; acc[3][3] += a3 * b.w;
    }
#pragma unroll
    for (int i = 0; i < 4; i++) {
        float4 o = make_float4(acc[i][0] * 0.125f, acc[i][1] * 0.125f,
                               acc[i][2] * 0.125f, acc[i][3] * 0.125f);
        *(float4*)(Sb + (size_t)(q0 + ty * 4 + i) * LL + k0 + tx * 4) = o;
    }
}

// ---------------- fused: additive mask + softmax + 3 diffusion steps, in-place on g_S ----
__global__ __launch_bounds__(256) void softmax_diff(const int* __restrict__ mask,
                                                    const float* __restrict__ kw) {
    __shared__ float pbuf[LL + 4];   // left-padded with 4 zeros for causal conv
    __shared__ float psb[LL];
    __shared__ float kvs[LL];
    __shared__ float w5[5];
    __shared__ float red[8];

    const int t = threadIdx.x;
    const int row = blockIdx.x;                 // (b*H + h)*L + q
    const int b = row / (HH * LL);
    float* Srow = g_S + (size_t)row * LL;
    const int* mrow = mask + b * LL;

    if (t == 0) {
        float mx = kw[0];
#pragma unroll
        for (int j = 1; j < 5; j++) mx = fmaxf(mx, kw[j]);
        float e[5], s = 0.f;
#pragma unroll
        for (int j = 0; j < 5; j++) { e[j] = __expf(kw[j] - mx); s += e[j]; }
#pragma unroll
        for (int j = 0; j < 5; j++) w5[j] = e[j] / s;
    }
    if (t < 4) pbuf[t] = 0.f;

    float v[PER];
    float mx = -3.4e38f;
#pragma unroll
    for (int r = 0; r < PER; r++) {
        int i = t + r * NTH;
        float kvv = (mrow[i] > 0) ? 1.f : 0.f;
        kvs[i] = kvv;
        float s = Srow[i] + ((kvv > 0.f) ? 0.f : -1e9f);
        v[r] = s;
        mx = fmaxf(mx, s);
    }
    mx = block_max(mx, red);

    float lsum = 0.f;
#pragma unroll
    for (int r = 0; r < PER; r++) {
        float e = __expf(v[r] - mx);
        pbuf[4 + t + r * NTH] = e;
        lsum += e;
    }
    float tot = block_sum(lsum, red);
    float inv = 1.f / tot;
#pragma unroll
    for (int r = 0; r < PER; r++) pbuf[4 + t + r * NTH] *= inv;

    for (int step = 0; step < 3; step++) {
        __syncthreads();   // all p updates visible before neighbor reads
        float ls = 0.f;
#pragma unroll
        for (int r = 0; r < PER; r++) {
            int i = t + r * NTH;
            float a = w5[0] * pbuf[i] + w5[1] * pbuf[i + 1] + w5[2] * pbuf[i + 2] +
                      w5[3] * pbuf[i + 3] + w5[4] * pbuf[i + 4];
            a *= kvs[i];
            psb[i] = a;
            ls += a;
        }
        float S = block_sum(ls, red);   // internal syncs fence psb before pbuf rewrite
        float rr = 0.02f / (S + 1e-9f);
#pragma unroll
        for (int r = 0; r < PER; r++) {
            int i = t + r * NTH;
            pbuf[4 + i] = 0.98f * pbuf[4 + i] + rr * psb[i];
        }
    }
#pragma unroll
    for (int r = 0; r < PER; r++) {
        int i = t + r * NTH;
        Srow[i] = pbuf[4 + i];
    }
}

// ---------------- attn = p @ V, per (b,h); C written interleaved [b,l,h*64+d] ----------
__global__ __launch_bounds__(256) void attn_gemm() {
    const int z = blockIdx.z;
    const int b = z >> 4;
    const int h = z & 15;
    const float* Aq = g_S + (size_t)z * LL * LL;
    const float* Vb = g_V + (size_t)z * LL * HDIM;
    float* Cb = g_attn + (size_t)b * LL * PP + h * HDIM;
    const int m0 = blockIdx.x * 64;

    __shared__ float As[64][20];
    __shared__ float Bs[16][68];

    const int t = threadIdx.x;
    const int tx = t & 15, ty = t >> 4;
    const int am = t >> 2, ak = (t & 3) * 4;
    const int bk = t >> 4, bn = (t & 15) * 4;

    float acc[4][4] = {};
    const float* Aptr = Aq + (size_t)(m0 + am) * LL + ak;
    const float* Bptr = Vb + (size_t)bk * HDIM + bn;

    for (int k0 = 0; k0 < LL; k0 += 16) {
        float4 a4 = *(const float4*)(Aptr + k0);
        *(float4*)&As[am][ak] = a4;
        float4 b4 = *(const float4*)(Bptr + (size_t)k0 * HDIM);
        *(float4*)&Bs[bk][bn] = b4;
        __syncthreads();
#pragma unroll
        for (int kk = 0; kk < 16; kk++) {
            float a0 = As[ty * 4 + 0][kk], a1 = As[ty * 4 + 1][kk];
            float a2 = As[ty * 4 + 2][kk], a3 = As[ty * 4 + 3][kk];
            float4 bv = *(float4*)&Bs[kk][tx * 4];
            acc[0][0] += a0 * bv.x; acc[0][1] += a0 * bv.y; acc[0][2] += a0 * bv.z; acc[0][3] += a0 * bv.w;
            acc[1][0] += a1 * bv.x; acc[1][1] += a1 * bv.y; acc[1][2] += a1 * bv.z; acc[1][3] += a1 * bv.w;
            acc[2][0] += a2 * bv.x; acc[2][1] += a2 * bv.y; acc[2][2] += a2 * bv.z; acc[2][3] += a2 * bv.w;
            acc[3][0] += a3 * bv.x; acc[3][1] += a3 * bv.y; acc[3][2] += a3 * bv.z; acc[3][3] += a3 * bv.w;
        }
        __syncthreads();
    }
#pragma unroll
    for (int i = 0; i < 4; i++) {
        float4 o = make_float4(acc[i][0], acc[i][1], acc[i][2], acc[i][3]);
        *(float4*)(Cb + (size_t)(m0 + ty * 4 + i) * PP + tx * 4) = o;
    }
}

// ---------------- launch ----------------
extern "C" void kernel_launch(void* const* d_in, const int* in_sizes, int n_in,
                              void* d_out, int out_size) {
    const float* hs = (const float*)d_in[0];
    const int* mask = (const int*)d_in[1];
    const float* Wq = (const float*)d_in[2];
    const float* bq = (const float*)d_in[3];
    const float* Wk = (const float*)d_in[4];
    const float* bk = (const float*)d_in[5];
    const float* Wv = (const float*)d_in[6];
    const float* bv = (const float*)d_in[7];
    const float* Wo = (const float*)d_in[8];
    const float* bo = (const float*)d_in[9];
    const float* kw = (const float*)d_in[10];

    dim3 gProj(PP / 64, (BB * LL) / 64);        // (16, 48)
    proj_gemm<<<gProj, 256>>>(hs, Wq, bq, nullptr, 0);
    proj_gemm<<<gProj, 256>>>(hs, Wk, bk, nullptr, 1);
    proj_gemm<<<gProj, 256>>>(hs, Wv, bv, nullptr, 2);

    scores_kernel<<<dim3(LL / 64, LL / 64, BB * HH), 256>>>();

    softmax_diff<<<BB * HH * LL, 256>>>(mask, kw);

    attn_gemm<<<dim3(LL / 64, 1, BB * HH), 256>>>();

    proj_gemm<<<gProj, 256>>>(nullptr, Wo, bo, (float*)d_out, 3);
}

// round 2
// speedup vs baseline: 1.3190x; 1.3190x over previous
#include <cuda_runtime.h>
#include <mma.h>
using namespace nvcuda;

#define BB 2
#define LL 1536
#define DD 1024
#define HH 16
#define PP 1024
#define HDIM 64
#define NTH 256
#define PER (LL / NTH)   // 6

// ---------------- device scratch ----------------
__device__ float g_Q[BB * HH * LL * HDIM];      // head-major [b,h,l,d]
__device__ float g_K[BB * HH * LL * HDIM];
__device__ float g_V[BB * HH * LL * HDIM];
__device__ float g_attn[BB * LL * PP];          // [b,l,h*64+d]
__device__ float g_S[BB * HH * LL * LL];        // 302 MB, scores -> p in-place

typedef wmma::fragment<wmma::matrix_a, 16, 16, 8, wmma::precision::tf32, wmma::row_major> FragA;
typedef wmma::fragment<wmma::matrix_b, 16, 16, 8, wmma::precision::tf32, wmma::row_major> FragB;
typedef wmma::fragment<wmma::matrix_b, 16, 16, 8, wmma::precision::tf32, wmma::col_major> FragBc;
typedef wmma::fragment<wmma::accumulator, 16, 16, 8, float> FragC;

__device__ __forceinline__ void cvt_tf32_a(FragA& f) {
#pragma unroll
    for (int e = 0; e < f.num_elements; e++) f.x[e] = wmma::__float_to_tf32(f.x[e]);
}
__device__ __forceinline__ void cvt_tf32_b(FragB& f) {
#pragma unroll
    for (int e = 0; e < f.num_elements; e++) f.x[e] = wmma::__float_to_tf32(f.x[e]);
}
__device__ __forceinline__ void cvt_tf32_bc(FragBc& f) {
#pragma unroll
    for (int e = 0; e < f.num_elements; e++) f.x[e] = wmma::__float_to_tf32(f.x[e]);
}

// ---------------- projection GEMM (tf32 wmma): C = A @ W + bias ----------------
// A [3072,1024] row-major, W [1024,1024] row-major.
// mode 0/1/2: write Q/K/V head-major. mode 3: flat fp32 to Cout (A = g_attn).
__global__ __launch_bounds__(256) void proj_wmma(const float* __restrict__ Ain,
                                                 const float* __restrict__ W,
                                                 const float* __restrict__ bias,
                                                 float* __restrict__ Cout, int mode) {
    const float* A = (mode == 3) ? g_attn : Ain;
    float* C;
    if (mode == 0) C = g_Q;
    else if (mode == 1) C = g_K;
    else if (mode == 2) C = g_V;
    else C = Cout;

    __shared__ float As[128][36];     // [m][k]
    __shared__ float Bs[32][132];     // [k][n]
    __shared__ float BiasT[16][132];  // 16 replicated bias rows

    const int m0 = blockIdx.y * 128;
    const int n0 = blockIdx.x * 128;
    const int t = threadIdx.x;
    const int warp = t >> 5;
    const int wm = (warp & 3) * 32;
    const int wn = (warp >> 2) * 64;

    // fill bias tile (16 rows x 128 cols)
#pragma unroll
    for (int r = 0; r < 2; r++) {
        int idx = t + r * 256;
        int row = idx >> 5;
        int col = (idx & 31) << 2;
        *(float4*)&BiasT[row][col] = *(const float4*)(bias + n0 + col);
    }

    FragC c[2][4];
#pragma unroll
    for (int i = 0; i < 2; i++)
#pragma unroll
        for (int j = 0; j < 4; j++) wmma::fill_fragment(c[i][j], 0.f);

    for (int k0 = 0; k0 < DD; k0 += 32) {
#pragma unroll
        for (int r = 0; r < 4; r++) {
            int idx = t + r * 256;
            int row = idx >> 3;
            int col = (idx & 7) << 2;
            *(float4*)&As[row][col] = *(const float4*)(A + (size_t)(m0 + row) * DD + k0 + col);
        }
#pragma unroll
        for (int r = 0; r < 4; r++) {
            int idx = t + r * 256;
            int row = idx >> 5;
            int col = (idx & 31) << 2;
            *(float4*)&Bs[row][col] = *(const float4*)(W + (size_t)(k0 + row) * PP + n0 + col);
        }
        __syncthreads();
#pragma unroll
        for (int kk = 0; kk < 32; kk += 8) {
            FragA a[2];
            FragB b[4];
#pragma unroll
            for (int i = 0; i < 2; i++) {
                wmma::load_matrix_sync(a[i], &As[wm + i * 16][kk], 36);
                cvt_tf32_a(a[i]);
            }
#pragma unroll
            for (int j = 0; j < 4; j++) {
                wmma::load_matrix_sync(b[j], &Bs[kk][wn + j * 16], 132);
                cvt_tf32_b(b[j]);
            }
#pragma unroll
            for (int i = 0; i < 2; i++)
#pragma unroll
                for (int j = 0; j < 4; j++) wmma::mma_sync(c[i][j], a[i], b[j], c[i][j]);
        }
        __syncthreads();
    }

    // add bias via accumulator-layout fragment of the replicated bias tile
#pragma unroll
    for (int i = 0; i < 2; i++)
#pragma unroll
        for (int j = 0; j < 4; j++) {
            FragC bf;
            wmma::load_matrix_sync(bf, &BiasT[0][wn + j * 16], 132, wmma::mem_row_major);
#pragma unroll
            for (int e = 0; e < bf.num_elements; e++) c[i][j].x[e] += bf.x[e];
        }

    if (mode <= 2) {
        const int b = m0 / LL;
        const int l0 = m0 - b * LL;
        const int h = (n0 + wn) >> 6;
        float* base = C + (((size_t)(b * HH + h)) * LL + l0 + wm) * HDIM;
#pragma unroll
        for (int i = 0; i < 2; i++)
#pragma unroll
            for (int j = 0; j < 4; j++)
                wmma::store_matrix_sync(base + (size_t)(i * 16) * HDIM + j * 16, c[i][j],
                                        HDIM, wmma::mem_row_major);
    } else {
        float* base = C + (size_t)(m0 + wm) * PP + n0 + wn;
#pragma unroll
        for (int i = 0; i < 2; i++)
#pragma unroll
            for (int j = 0; j < 4; j++)
                wmma::store_matrix_sync(base + (size_t)(i * 16) * PP + j * 16, c[i][j],
                                        PP, wmma::mem_row_major);
    }
}

// ---------------- scores (tf32 wmma): S = (Q/8) @ K^T ----------------
__global__ __launch_bounds__(256) void scores_wmma() {
    const int z = blockIdx.z;
    const float* Qb = g_Q + (size_t)z * LL * HDIM;
    const float* Kb = g_K + (size_t)z * LL * HDIM;
    float* Sb = g_S + (size_t)z * LL * LL;
    const int q0 = blockIdx.y * 128;
    const int n0 = blockIdx.x * 128;

    __shared__ float As[128][36];   // [q][d]
    __shared__ float Bs[128][36];   // [n][d] -> col_major frags

    const int t = threadIdx.x;
    const int warp = t >> 5;
    const int wm = (warp & 3) * 32;
    const int wn = (warp >> 2) * 64;

    FragC c[2][4];
#pragma unroll
    for (int i = 0; i < 2; i++)
#pragma unroll
        for (int j = 0; j < 4; j++) wmma::fill_fragment(c[i][j], 0.f);

    for (int d0 = 0; d0 < HDIM; d0 += 32) {
#pragma unroll
        for (int r = 0; r < 4; r++) {
            int idx = t + r * 256;
            int row = idx >> 3;
            int col = (idx & 7) << 2;
            float4 q4 = *(const float4*)(Qb + (size_t)(q0 + row) * HDIM + d0 + col);
            q4.x *= 0.125f; q4.y *= 0.125f; q4.z *= 0.125f; q4.w *= 0.125f;
            *(float4*)&As[row][col] = q4;
            float4 k4 = *(const float4*)(Kb + (size_t)(n0 + row) * HDIM + d0 + col);
            *(float4*)&Bs[row][col] = k4;
        }
        __syncthreads();
#pragma unroll
        for (int kk = 0; kk < 32; kk += 8) {
            FragA a[2];
            FragBc b[4];
#pragma unroll
            for (int i = 0; i < 2; i++) {
                wmma::load_matrix_sync(a[i], &As[wm + i * 16][kk], 36);
                cvt_tf32_a(a[i]);
            }
#pragma unroll
            for (int j = 0; j < 4; j++) {
                wmma::load_matrix_sync(b[j], &Bs[wn + j * 16][kk], 36);
                cvt_tf32_bc(b[j]);
            }
#pragma unroll
            for (int i = 0; i < 2; i++)
#pragma unroll
                for (int j = 0; j < 4; j++) wmma::mma_sync(c[i][j], a[i], b[j], c[i][j]);
        }
        __syncthreads();
    }

    float* base = Sb + (size_t)(q0 + wm) * LL + n0 + wn;
#pragma unroll
    for (int i = 0; i < 2; i++)
#pragma unroll
        for (int j = 0; j < 4; j++)
            wmma::store_matrix_sync(base + (size_t)(i * 16) * LL + j * 16, c[i][j],
                                    LL, wmma::mem_row_major);
}

// ---------------- attn = p @ V (tf32 wmma), 128 threads, block tile 128x64 ----------------
__global__ __launch_bounds__(128) void attn_wmma() {
    const int z = blockIdx.z;
    const int b = z >> 4;
    const int h = z & 15;
    const float* Pb = g_S + (size_t)z * LL * LL;
    const float* Vb = g_V + (size_t)z * LL * HDIM;
    float* Cb = g_attn + (size_t)b * LL * PP + h * HDIM;
    const int m0 = blockIdx.x * 128;

    __shared__ float As[128][36];   // [m][k]
    __shared__ float Bs[32][68];    // [k][n]

    const int t = threadIdx.x;
    const int warp = t >> 5;
    const int wm = warp * 32;

    FragC c[2][4];
#pragma unroll
    for (int i = 0; i < 2; i++)
#pragma unroll
        for (int j = 0; j < 4; j++) wmma::fill_fragment(c[i][j], 0.f);

    for (int k0 = 0; k0 < LL; k0 += 32) {
#pragma unroll
        for (int r = 0; r < 8; r++) {
            int idx = t + r * 128;
            int row = idx >> 3;
            int col = (idx & 7) << 2;
            *(float4*)&As[row][col] = *(const float4*)(Pb + (size_t)(m0 + row) * LL + k0 + col);
        }
#pragma unroll
        for (int r = 0; r < 4; r++) {
            int idx = t + r * 128;
            int row = idx >> 4;
            int col = (idx & 15) << 2;
            *(float4*)&Bs[row][col] = *(const float4*)(Vb + (size_t)(k0 + row) * HDIM + col);
        }
        __syncthreads();
#pragma unroll
        for (int kk = 0; kk < 32; kk += 8) {
            FragA a[2];
            FragB bfrag[4];
#pragma unroll
            for (int i = 0; i < 2; i++) {
                wmma::load_matrix_sync(a[i], &As[wm + i * 16][kk], 36);
                cvt_tf32_a(a[i]);
            }
#pragma unroll
            for (int j = 0; j < 4; j++) {
                wmma::load_matrix_sync(bfrag[j], &Bs[kk][j * 16], 68);
                cvt_tf32_b(bfrag[j]);
            }
#pragma unroll
            for (int i = 0; i < 2; i++)
#pragma unroll
                for (int j = 0; j < 4; j++) wmma::mma_sync(c[i][j], a[i], bfrag[j], c[i][j]);
        }
        __syncthreads();
    }

    float* base = Cb + (size_t)(m0 + wm) * PP;
#pragma unroll
    for (int i = 0; i < 2; i++)
#pragma unroll
        for (int j = 0; j < 4; j++)
            wmma::store_matrix_sync(base + (size_t)(i * 16) * PP + j * 16, c[i][j],
                                    PP, wmma::mem_row_major);
}

// ---------------- block reductions (256 threads) ----------------
__device__ __forceinline__ float block_sum(float v, float* red) {
    __syncthreads();
#pragma unroll
    for (int o = 16; o > 0; o >>= 1) v += __shfl_xor_sync(0xffffffffu, v, o);
    if ((threadIdx.x & 31) == 0) red[threadIdx.x >> 5] = v;
    __syncthreads();
    float s = 0.f;
#pragma unroll
    for (int j = 0; j < 8; j++) s += red[j];
    return s;
}

__device__ __forceinline__ float block_max(float v, float* red) {
    __syncthreads();
#pragma unroll
    for (int o = 16; o > 0; o >>= 1) v = fmaxf(v, __shfl_xor_sync(0xffffffffu, v, o));
    if ((threadIdx.x & 31) == 0) red[threadIdx.x >> 5] = v;
    __syncthreads();
    float s = red[0];
#pragma unroll
    for (int j = 1; j < 8; j++) s = fmaxf(s, red[j]);
    return s;
}

// ---------------- fused: mask + softmax + 3 diffusion steps, in-place on g_S ----------
__global__ __launch_bounds__(256) void softmax_diff(const int* __restrict__ mask,
                                                    const float* __restrict__ kw) {
    __shared__ float pbuf[LL + 4];
    __shared__ float psb[LL];
    __shared__ float kvs[LL];
    __shared__ float w5[5];
    __shared__ float red[8];

    const int t = threadIdx.x;
    const int row = blockIdx.x;
    const int b = row / (HH * LL);
    float* Srow = g_S + (size_t)row * LL;
    const int* mrow = mask + b * LL;

    if (t == 0) {
        float mx = kw[0];
#pragma unroll
        for (int j = 1; j < 5; j++) mx = fmaxf(mx, kw[j]);
        float e[5], s = 0.f;
#pragma unroll
        for (int j = 0; j < 5; j++) { e[j] = __expf(kw[j] - mx); s += e[j]; }
#pragma unroll
        for (int j = 0; j < 5; j++) w5[j] = e[j] / s;
    }
    if (t < 4) pbuf[t] = 0.f;

    float v[PER];
    float mx = -3.4e38f;
#pragma unroll
    for (int r = 0; r < PER; r++) {
        int i = t + r * NTH;
        float kvv = (mrow[i] > 0) ? 1.f : 0.f;
        kvs[i] = kvv;
        float s = Srow[i] + ((kvv > 0.f) ? 0.f : -1e9f);
        v[r] = s;
        mx = fmaxf(mx, s);
    }
    mx = block_max(mx, red);

    float lsum = 0.f;
#pragma unroll
    for (int r = 0; r < PER; r++) {
        float e = __expf(v[r] - mx);
        pbuf[4 + t + r * NTH] = e;
        lsum += e;
    }
    float tot = block_sum(lsum, red);
    float inv = 1.f / tot;
#pragma unroll
    for (int r = 0; r < PER; r++) pbuf[4 + t + r * NTH] *= inv;

    for (int step = 0; step < 3; step++) {
        __syncthreads();
        float ls = 0.f;
#pragma unroll
        for (int r = 0; r < PER; r++) {
            int i = t + r * NTH;
            float a = w5[0] * pbuf[i] + w5[1] * pbuf[i + 1] + w5[2] * pbuf[i + 2] +
                      w5[3] * pbuf[i + 3] + w5[4] * pbuf[i + 4];
            a *= kvs[i];
            psb[i] = a;
            ls += a;
        }
        float S = block_sum(ls, red);
        float rr = 0.02f / (S + 1e-9f);
#pragma unroll
        for (int r = 0; r < PER; r++) {
            int i = t + r * NTH;
            pbuf[4 + i] = 0.98f * pbuf[4 + i] + rr * psb[i];
        }
    }
#pragma unroll
    for (int r = 0; r < PER; r++) {
        int i = t + r * NTH;
        Srow[i] = pbuf[4 + i];
    }
}

// ---------------- launch ----------------
extern "C" void kernel_launch(void* const* d_in, const int* in_sizes, int n_in,
                              void* d_out, int out_size) {
    const float* hs = (const float*)d_in[0];
    const int* mask = (const int*)d_in[1];
    const float* Wq = (const float*)d_in[2];
    const float* bq = (const float*)d_in[3];
    const float* Wk = (const float*)d_in[4];
    const float* bk = (const float*)d_in[5];
    const float* Wv = (const float*)d_in[6];
    const float* bv = (const float*)d_in[7];
    const float* Wo = (const float*)d_in[8];
    const float* bo = (const float*)d_in[9];
    const float* kw = (const float*)d_in[10];

    dim3 gProj(PP / 128, (BB * LL) / 128);          // (8, 24)
    proj_wmma<<<gProj, 256>>>(hs, Wq, bq, nullptr, 0);
    proj_wmma<<<gProj, 256>>>(hs, Wk, bk, nullptr, 1);
    proj_wmma<<<gProj, 256>>>(hs, Wv, bv, nullptr, 2);

    scores_wmma<<<dim3(LL / 128, LL / 128, BB * HH), 256>>>();

    softmax_diff<<<BB * HH * LL, 256>>>(mask, kw);

    attn_wmma<<<dim3(LL / 128, 1, BB * HH), 128>>>();

    proj_wmma<<<gProj, 256>>>(nullptr, Wo, bo, (float*)d_out, 3);
}